// round 9
// baseline (speedup 1.0000x reference)
#include <cuda_runtime.h>
#include <cstdint>
#include <cstddef>

#define NB    4
#define NSRC  16384
#define NTGT  4096
#define KNN   32
#define FULLM 0xffffffffu

// spatial grid
#define G     32
#define NCELL (G*G*G)
#define LB    6.0f
#define GH    0.375f
#define INVH  (1.0f/GH)

// staging
#define CAP     2400
#define MAXROWS 64

// Output layout (flattened concat, all float32):
#define OFF_PATCH 0
#define OFF_IDX   1572864
#define OFF_SIZE  2621440
#define OFF_RAD   2637824
#define OFF_DIST  2637828

// __device__ scratch (no allocations allowed)
__device__ int    g_cnt [NB * NCELL];
__device__ int    g_cur [NB * NCELL];
__device__ int    g_start[NB * (NCELL + 1)];
__device__ float4 g_pts[NB * NSRC];   // (x, y, z, idx-as-float-bits), cell-sorted
__device__ int    g_tcnt[NB * NCELL];
__device__ int    g_tcur[NB * NCELL];
__device__ int    g_tstart[NB * (NCELL + 1)];
__device__ int    g_tord[NB * NTGT];  // cell-sorted target order (local ids)

__device__ __forceinline__ int cellcoord(float v) {
    int c = (int)floorf((v + LB) * INVH);
    return min(G - 1, max(0, c));
}

__global__ void k_zero() {
    int i = blockIdx.x * blockDim.x + threadIdx.x;
    if (i < NB * NCELL) { g_cnt[i] = 0; g_tcnt[i] = 0; }
}

__global__ void k_count(const float* __restrict__ src,
                        const float* __restrict__ tgt) {
    int i = blockIdx.x * blockDim.x + threadIdx.x;
    if (i < NB * NSRC) {
        int b = i / NSRC;
        float x = src[3 * i], y = src[3 * i + 1], z = src[3 * i + 2];
        int cell = (cellcoord(z) * G + cellcoord(y)) * G + cellcoord(x);
        atomicAdd(&g_cnt[b * NCELL + cell], 1);
    }
    if (i < NB * NTGT) {
        int b = i / NTGT;
        float x = tgt[3 * i], y = tgt[3 * i + 1], z = tgt[3 * i + 2];
        int cell = (cellcoord(z) * G + cellcoord(y)) * G + cellcoord(x);
        atomicAdd(&g_tcnt[b * NCELL + cell], 1);
    }
}

#define CPT (NCELL / 1024)
// blocks 0..3: source grids; blocks 4..7: target grids
__global__ void k_scan() {
    __shared__ int sm[1024];
    const bool is_t = (blockIdx.x >= NB);
    const int b = is_t ? (blockIdx.x - NB) : blockIdx.x;
    const int* cnt = (is_t ? g_tcnt : g_cnt) + b * NCELL;
    int* start = (is_t ? g_tstart : g_start) + b * (NCELL + 1);
    int* cur   = (is_t ? g_tcur  : g_cur ) + b * NCELL;
    const int tot = is_t ? NTGT : NSRC;
    int t = threadIdx.x;
    int s = 0;
    #pragma unroll
    for (int c = 0; c < CPT; c++) s += cnt[t * CPT + c];
    sm[t] = s; __syncthreads();
    for (int off = 1; off < 1024; off <<= 1) {
        int v = (t >= off) ? sm[t - off] : 0;
        __syncthreads();
        sm[t] += v;
        __syncthreads();
    }
    int run = sm[t] - s;
    #pragma unroll
    for (int c = 0; c < CPT; c++) {
        int id = t * CPT + c;
        start[id] = run; cur[id] = run;
        run += cnt[id];
    }
    if (t == 1023) start[NCELL] = tot;
}

__global__ void k_scatter(const float* __restrict__ src,
                          const float* __restrict__ tgt) {
    int i = blockIdx.x * blockDim.x + threadIdx.x;
    if (i < NB * NSRC) {
        int b = i / NSRC;
        float x = src[3 * i], y = src[3 * i + 1], z = src[3 * i + 2];
        int cell = (cellcoord(z) * G + cellcoord(y)) * G + cellcoord(x);
        int pos = atomicAdd(&g_cur[b * NCELL + cell], 1);
        g_pts[b * NSRC + pos] = make_float4(x, y, z, __int_as_float(i - b * NSRC));
    }
    if (i < NB * NTGT) {
        int b = i / NTGT;
        float x = tgt[3 * i], y = tgt[3 * i + 1], z = tgt[3 * i + 2];
        int cell = (cellcoord(z) * G + cellcoord(y)) * G + cellcoord(x);
        int pos = atomicAdd(&g_tcur[b * NCELL + cell], 1);
        g_tord[b * NTGT + pos] = i - b * NTGT;
    }
}

// Block of 8 warps handles 8 consecutive cell-sorted targets. The union of
// their 27-cell boxes is staged in SMEM once; every warp streams the staged
// set linearly (supersets are safe: lex (value,index) top-K is min-invariant
// and scan-order-free == jax top_k tie-break). Rare unresolved targets
// escalate via shells clipped against the staged box (no duplicates).
__global__ __launch_bounds__(256) void k_query(const float* __restrict__ src,
                                               const float* __restrict__ tgt,
                                               float* __restrict__ out) {
    __shared__ float4 s_cand[CAP];
    __shared__ int s_rp0 [MAXROWS];
    __shared__ int s_rpre[MAXROWS];
    __shared__ int s_box[6];        // xa xb ya yb za zb
    __shared__ int s_info[3];       // nrows, nyr, fall
    __shared__ int s_p0 [8][32], s_pre[8][32];
    __shared__ int s_tc[8][3];

    const int tid  = threadIdx.x;
    const int w    = tid >> 5;
    const int lane = tid & 31;
    const int b    = (blockIdx.x * 8) / NTGT;

    // ---- block setup: cells of the 8 targets, union box ----
    if (tid < 8) {
        const int tg2 = b * NTGT + g_tord[blockIdx.x * 8 + tid];
        s_tc[tid][0] = cellcoord(tgt[3 * tg2]);
        s_tc[tid][1] = cellcoord(tgt[3 * tg2 + 1]);
        s_tc[tid][2] = cellcoord(tgt[3 * tg2 + 2]);
    }
    __syncthreads();
    if (tid == 0) {
        int mnx = s_tc[0][0], mxx = mnx, mny = s_tc[0][1], mxy = mny;
        int mnz = s_tc[0][2], mxz = mnz;
        #pragma unroll
        for (int t = 1; t < 8; ++t) {
            mnx = min(mnx, s_tc[t][0]); mxx = max(mxx, s_tc[t][0]);
            mny = min(mny, s_tc[t][1]); mxy = max(mxy, s_tc[t][1]);
            mnz = min(mnz, s_tc[t][2]); mxz = max(mxz, s_tc[t][2]);
        }
        const int xa = max(mnx - 1, 0), xb = min(mxx + 1, G - 1);
        const int ya = max(mny - 1, 0), yb = min(mxy + 1, G - 1);
        const int za = max(mnz - 1, 0), zb = min(mxz + 1, G - 1);
        s_box[0] = xa; s_box[1] = xb; s_box[2] = ya;
        s_box[3] = yb; s_box[4] = za; s_box[5] = zb;
        const int nyr = yb - ya + 1;
        const int nrows = (zb - za + 1) * nyr;
        s_info[0] = nrows; s_info[1] = nyr;
        s_info[2] = (nrows > MAXROWS) ? 1 : 0;
    }
    __syncthreads();

    const int*    cstart = g_start + b * (NCELL + 1);
    const float4* pts    = g_pts + b * NSRC;

    int fall = s_info[2];
    const int nrows = s_info[0], nyr = s_info[1];
    const int xa = s_box[0], xb = s_box[1], ya = s_box[2];
    const int yb = s_box[3], za = s_box[4], zb = s_box[5];

    int T = 0;
    if (!fall) {
        // ---- row ranges + prefix (threads 0..63) ----
        int p0v = 0, len = 0;
        if (tid < nrows) {
            const int zc = za + tid / nyr;
            const int yc = ya + tid % nyr;
            const int cb = (zc * G + yc) * G;
            p0v = cstart[cb + xa];
            len = cstart[cb + xb + 1] - p0v;
        }
        if (tid < MAXROWS) s_rpre[tid] = len;
        __syncthreads();
        for (int off = 1; off < MAXROWS; off <<= 1) {
            int v = 0;
            if (tid < MAXROWS && tid >= off) v = s_rpre[tid - off];
            __syncthreads();
            if (tid < MAXROWS) s_rpre[tid] += v;
            __syncthreads();
        }
        T = s_rpre[MAXROWS - 1];
        __syncthreads();
        if (tid < MAXROWS) {
            s_rpre[tid] -= len;        // exclusive prefix; padded rows -> T
            s_rp0[tid] = p0v;
        }
        if (tid == 0 && T > CAP) s_info[2] = 1;
        __syncthreads();
        fall = s_info[2];
        if (!fall) {
            for (int i = tid; i < T; i += 256) {
                int lo = 0;            // max r with s_rpre[r] <= i
                #pragma unroll
                for (int step = 32; step; step >>= 1) {
                    const int cand = lo + step;
                    if (cand < MAXROWS && s_rpre[cand] <= i) lo = cand;
                }
                s_cand[i] = pts[s_rp0[lo] + (i - s_rpre[lo])];
            }
        }
        __syncthreads();
    }

    // ---- per-warp query ----
    const int tg = b * NTGT + g_tord[blockIdx.x * 8 + w];
    const float px = tgt[3 * tg], py = tgt[3 * tg + 1], pz = tgt[3 * tg + 2];
    const float tt = __fadd_rn(__fadd_rn(__fmul_rn(px, px), __fmul_rn(py, py)),
                               __fmul_rn(pz, pz));
    const int cx = cellcoord(px), cy = cellcoord(py), cz = cellcoord(pz);
    float exo = fmaxf(fmaxf(-LB - px, px - LB), 0.0f);
    float eyo = fmaxf(fmaxf(-LB - py, py - LB), 0.0f);
    float ezo = fmaxf(fmaxf(-LB - pz, pz - LB), 0.0f);
    const float e = sqrtf(exo * exo + eyo * eyo + ezo * ezo);

    const float INF  = __int_as_float(0x7f800000);
    const int   IMAX = 0x7fffffff;
    float lv = INF; int li = IMAX;
    float thr_v = INF; int thr_i = IMAX;
    bool filled = false;

    const int dmax = max(max(max(cx, G - 1 - cx), max(cy, G - 1 - cy)),
                         max(cz, G - 1 - cz));

    // consume one warp-batch of candidates (sqv, jj) under lex order
    auto consume = [&](float sqv, int jj) {
        if (!filled) {
            #pragma unroll
            for (int kk = 2; kk <= 32; kk <<= 1) {
                #pragma unroll
                for (int j = kk >> 1; j > 0; j >>= 1) {
                    const float ov = __shfl_xor_sync(FULLM, sqv, j);
                    const int   oi = __shfl_xor_sync(FULLM, jj,  j);
                    const bool dirAsc = ((lane & kk) == 0);
                    const bool otherLess = (ov < sqv) || (ov == sqv && oi < jj);
                    const bool lower = (lane & j) == 0;
                    const bool keepOther = lower ? (dirAsc ? otherLess : !otherLess)
                                                 : (dirAsc ? !otherLess : otherLess);
                    if (keepOther) { sqv = ov; jj = oi; }
                }
            }
            lv = sqv; li = jj;
            thr_v = __shfl_sync(FULLM, lv, 31);
            thr_i = __shfl_sync(FULLM, li, 31);
            filled = true;
        } else {
            const bool acc = (sqv < thr_v) || (sqv == thr_v && jj < thr_i);
            unsigned ball = __ballot_sync(FULLM, acc);
            if (ball) {
                do {
                    const int   sl = __ffs(ball) - 1;
                    ball &= ball - 1;
                    const float nv = __shfl_sync(FULLM, sqv, sl);
                    const int   nj = __shfl_sync(FULLM, jj,  sl);
                    const unsigned le =
                        __ballot_sync(FULLM, (lv < nv) || (lv == nv && li < nj));
                    const int ppos = __popc(le);
                    if (ppos < 32) {
                        const float pv = __shfl_up_sync(FULLM, lv, 1);
                        const int   pj = __shfl_up_sync(FULLM, li, 1);
                        if (lane > ppos)       { lv = pv; li = pj; }
                        else if (lane == ppos) { lv = nv; li = nj; }
                    }
                } while (ball);
                thr_v = __shfl_sync(FULLM, lv, 31);
                thr_i = __shfl_sync(FULLM, li, 31);
            }
        }
    };

    auto evalS = [&](const float4& S, float& sqv, int& jj) {
        jj = __float_as_int(S.w);
        const float ss = __fadd_rn(__fadd_rn(__fmul_rn(S.x, S.x),
                                             __fmul_rn(S.y, S.y)),
                                   __fmul_rn(S.z, S.z));
        const float dot = __fmaf_rn(pz, S.z, __fmaf_rn(py, S.y, __fmul_rn(px, S.x)));
        sqv = __fadd_rn(__fsub_rn(tt, __fmul_rn(2.0f, dot)), ss);
    };

    int dstart = -1;
    if (!fall) {
        // ---- staged stream (LDS, linear, no search) ----
        for (int base = 0; base < T; base += 32) {
            const int pos = base + lane;
            float sqv = INF; int jj = IMAX;
            if (pos < T) evalS(s_cand[pos], sqv, jj);
            consume(sqv, jj);
        }
        int cov = 1 << 28;
        if (xa > 0)     cov = min(cov, cx - xa);
        if (xb < G - 1) cov = min(cov, xb - cx);
        if (ya > 0)     cov = min(cov, cy - ya);
        if (yb < G - 1) cov = min(cov, yb - cy);
        if (za > 0)     cov = min(cov, cz - za);
        if (zb < G - 1) cov = min(cov, zb - cz);
        dstart = cov;
    }

    // ---- escalation shells (box-clipped), also full path when fall ----
    for (int d = dstart;;) {
        if (d >= 0) {
            const float dm = __fmaf_rn((float)d, GH, -e);
            if (dm > 0.0f && thr_v < dm * dm) break;   // strict: index ties
            if (d >= dmax) break;
        }
        ++d;
        const int nseg = (d == 0) ? 1 : (8 * d + 2 * (2 * d - 1) * (2 * d - 1));
        for (int bk = 0; bk < 2 * nseg; bk += 32) {
            const int k = bk + lane;
            bool valid = (k < 2 * nseg);
            const int piece = (k >= nseg) ? 1 : 0;
            const int kk = k - piece * nseg;
            int zc = cz, yc = cy, x0 = cx, x1 = cx;
            if (valid && d > 0) {
                if (kk < 8 * d) {
                    const int side = kk / (2 * d), off = kk % (2 * d);
                    int zo, yo;
                    if      (side == 0) { zo = -d; yo = -d + off; }
                    else if (side == 1) { yo =  d; zo = -d + off; }
                    else if (side == 2) { zo =  d; yo =  d - off; }
                    else                { yo = -d; zo =  d - off; }
                    zc = cz + zo; yc = cy + yo;
                    x0 = max(cx - d, 0); x1 = min(cx + d, G - 1);
                } else {
                    const int k2 = kk - 8 * d;
                    const int w2 = 2 * d - 1;
                    const int r = k2 >> 1, side2 = k2 & 1;
                    zc = cz + (-d + 1 + r / w2);
                    yc = cy + (-d + 1 + r % w2);
                    const int x = side2 ? (cx + d) : (cx - d);
                    x0 = x1 = x;
                    if (x < 0 || x >= G) valid = false;
                }
                if (zc < 0 || zc >= G || yc < 0 || yc >= G) valid = false;
            }
            if (valid) {
                const bool inBoxYZ = (!fall) && zc >= za && zc <= zb &&
                                     yc >= ya && yc <= yb;
                if (inBoxYZ) {
                    if (piece == 0) x1 = min(x1, xa - 1);
                    else            x0 = max(x0, xb + 1);
                } else if (piece == 1) valid = false;
                if (x0 > x1) valid = false;
            }
            int p0 = 0, len = 0;
            if (valid) {
                const int cb = (zc * G + yc) * G;
                p0  = cstart[cb + x0];
                len = cstart[cb + x1 + 1] - p0;
            }
            // exclusive warp scan of len
            int pre = len;
            #pragma unroll
            for (int off = 1; off < 32; off <<= 1) {
                int n = __shfl_up_sync(FULLM, pre, off);
                if (lane >= off) pre += n;
            }
            const int total = __shfl_sync(FULLM, pre, 31);
            pre -= len;
            s_p0 [w][lane] = p0;
            s_pre[w][lane] = pre;
            __syncwarp(FULLM);
            if (total == 0) continue;

            for (int base = 0; base < total; base += 32) {
                const int pos = base + lane;
                float sqv = INF; int jj = IMAX;
                if (pos < total) {
                    int lo = 0;
                    #pragma unroll
                    for (int step = 16; step; step >>= 1) {
                        const int cand = lo + step;
                        if (cand < 32 && s_pre[w][cand] <= pos) lo = cand;
                    }
                    const int ii = s_p0[w][lo] + (pos - s_pre[w][lo]);
                    evalS(pts[ii], sqv, jj);
                }
                consume(sqv, jj);
            }
        }
    }

    // ---- outputs ----
    const float rad  = 0.2f;
    const float rad2 = __fmul_rn(rad, rad);
    const bool  mask = (rad2 >= lv);

    float gx = 0.0f, gy = 0.0f, gz = 0.0f;
    if (mask) {
        const float* sp = src + (size_t)(b * NSRC + li) * 3;
        gx = __fdiv_rn(sp[0], rad);
        gy = __fdiv_rn(sp[1], rad);
        gz = __fdiv_rn(sp[2], rad);
    }
    const float tdx = __fdiv_rn(px, rad);
    const float tdy = __fdiv_rn(py, rad);
    const float tdz = __fdiv_rn(pz, rad);

    const size_t ee = (size_t)tg * KNN + lane;

    float* patches = out + OFF_PATCH;
    patches[3 * ee + 0] = __fsub_rn(gx, tdx);
    patches[3 * ee + 1] = __fsub_rn(gy, tdy);
    patches[3 * ee + 2] = __fsub_rn(gz, tdz);

    float* idxf = out + OFF_IDX;
    idxf[2 * ee + 0] = (float)b;
    idxf[2 * ee + 1] = (float)(mask ? li : -1);

    float* pdist = out + OFF_DIST;
    pdist[ee] = __fdiv_rn(__fsqrt_rn(fmaxf(lv, 1e-9f)), rad);

    const unsigned mball = __ballot_sync(FULLM, mask);
    if (lane == 0) {
        float* psize = out + OFF_SIZE;
        psize[tg] = (float)__popc(mball);
    }

    if (blockIdx.x == 0 && tid < NB) {
        float* prad = out + OFF_RAD;
        prad[tid] = rad;
    }
}

extern "C" void kernel_launch(void* const* d_in, const int* in_sizes, int n_in,
                              void* d_out, int out_size) {
    const float* src = (const float*)d_in[0];
    const float* tgt = (const float*)d_in[1];
    if (n_in >= 2 && in_sizes[0] == NB * NTGT * 3 && in_sizes[1] == NB * NSRC * 3) {
        src = (const float*)d_in[1];
        tgt = (const float*)d_in[0];
    }
    float* out = (float*)d_out;

    k_zero   <<<(NB * NCELL + 255) / 256, 256>>>();
    k_count  <<<(NB * NSRC + 255) / 256, 256>>>(src, tgt);
    k_scan   <<<2 * NB, 1024>>>();
    k_scatter<<<(NB * NSRC + 255) / 256, 256>>>(src, tgt);
    k_query  <<<(NB * NTGT) / 8, 256>>>(src, tgt, out);
}

// round 10
// speedup vs baseline: 1.1833x; 1.1833x over previous
#include <cuda_runtime.h>
#include <cstdint>
#include <cstddef>

#define NB    4
#define NSRC  16384
#define NTGT  4096
#define KNN   32
#define FULLM 0xffffffffu

// spatial grid
#define G     32
#define NCELL (G*G*G)
#define LB    6.0f
#define GH    0.375f
#define INVH  (1.0f/GH)

// per-warp staging
#define WPB   4
#define CAPW  512

// Output layout (flattened concat, all float32):
#define OFF_PATCH 0
#define OFF_IDX   1572864
#define OFF_SIZE  2621440
#define OFF_RAD   2637824
#define OFF_DIST  2637828

// __device__ scratch (no allocations allowed)
__device__ int    g_cnt[NB * NCELL];
__device__ int    g_cur[NB * NCELL];
__device__ int    g_start[NB * (NCELL + 1)];
__device__ float4 g_pts[NB * NSRC];   // (x, y, z, sumsq), cell-sorted
__device__ int    g_pidx[NB * NSRC];  // original within-batch index

__device__ __forceinline__ int cellcoord(float v) {
    int c = (int)floorf((v + LB) * INVH);
    return min(G - 1, max(0, c));
}

__global__ void k_zero() {
    int i = blockIdx.x * blockDim.x + threadIdx.x;
    if (i < NB * NCELL) g_cnt[i] = 0;
}

__global__ void k_count(const float* __restrict__ src) {
    int i = blockIdx.x * blockDim.x + threadIdx.x;
    if (i >= NB * NSRC) return;
    int b = i / NSRC;
    float x = src[3 * i], y = src[3 * i + 1], z = src[3 * i + 2];
    int cell = (cellcoord(z) * G + cellcoord(y)) * G + cellcoord(x);
    atomicAdd(&g_cnt[b * NCELL + cell], 1);
}

#define CPT (NCELL / 1024)
__global__ void k_scan() {
    __shared__ int sm[1024];
    int b = blockIdx.x, t = threadIdx.x;
    const int* cnt = g_cnt + b * NCELL;
    int* start = g_start + b * (NCELL + 1);
    int* cur   = g_cur + b * NCELL;
    int s = 0;
    #pragma unroll
    for (int c = 0; c < CPT; c++) s += cnt[t * CPT + c];
    sm[t] = s; __syncthreads();
    for (int off = 1; off < 1024; off <<= 1) {
        int v = (t >= off) ? sm[t - off] : 0;
        __syncthreads();
        sm[t] += v;
        __syncthreads();
    }
    int run = sm[t] - s;
    #pragma unroll
    for (int c = 0; c < CPT; c++) {
        int id = t * CPT + c;
        start[id] = run; cur[id] = run;
        run += cnt[id];
    }
    if (t == 1023) start[NCELL] = NSRC;
}

__global__ void k_scatter(const float* __restrict__ src) {
    int i = blockIdx.x * blockDim.x + threadIdx.x;
    if (i >= NB * NSRC) return;
    int b = i / NSRC;
    float x = src[3 * i], y = src[3 * i + 1], z = src[3 * i + 2];
    int cell = (cellcoord(z) * G + cellcoord(y)) * G + cellcoord(x);
    int pos = atomicAdd(&g_cur[b * NCELL + cell], 1);
    float ss = __fadd_rn(__fadd_rn(__fmul_rn(x, x), __fmul_rn(y, y)), __fmul_rn(z, z));
    g_pts[b * NSRC + pos]  = make_float4(x, y, z, ss);
    g_pidx[b * NSRC + pos] = i - b * NSRC;
}

// One warp per target. d<=1 box staged per-warp into SMEM (copy phase with
// independent iterations, then LDS-linear compute phase). Overflow and shells
// d>=2 use the R5 search+LDG path. Lex (value, index) sorted top-K == jax
// top_k tie-break under any scan order.
__global__ __launch_bounds__(128) void k_query(const float* __restrict__ src,
                                               const float* __restrict__ tgt,
                                               float* __restrict__ out) {
    __shared__ float4 s_buf[WPB][CAPW];
    __shared__ int s_p0 [WPB][32];
    __shared__ int s_pre[WPB][32];

    const int w    = threadIdx.x >> 5;
    const int lane = threadIdx.x & 31;
    const int tg   = blockIdx.x * WPB + w;
    const int b    = tg / NTGT;

    const float px = tgt[3 * tg], py = tgt[3 * tg + 1], pz = tgt[3 * tg + 2];
    const float tt = __fadd_rn(__fadd_rn(__fmul_rn(px, px), __fmul_rn(py, py)),
                               __fmul_rn(pz, pz));

    const int cx = cellcoord(px), cy = cellcoord(py), cz = cellcoord(pz);
    float exo = fmaxf(fmaxf(-LB - px, px - LB), 0.0f);
    float eyo = fmaxf(fmaxf(-LB - py, py - LB), 0.0f);
    float ezo = fmaxf(fmaxf(-LB - pz, pz - LB), 0.0f);
    const float e = sqrtf(exo * exo + eyo * eyo + ezo * ezo);

    const float INF  = __int_as_float(0x7f800000);
    const int   IMAX = 0x7fffffff;
    float lv = INF; int li = IMAX;
    float thr_v = INF; int thr_i = IMAX;
    bool filled = false;

    const int*    cstart = g_start + b * (NCELL + 1);
    const float4* pts    = g_pts + b * NSRC;
    const int*    pidx   = g_pidx + b * NSRC;

    const int dmax = max(max(max(cx, G - 1 - cx), max(cy, G - 1 - cy)),
                         max(cz, G - 1 - cz));

    // consume one warp-batch of candidates under lex (value, index) order
    auto consume = [&](float sqv, int jj) {
        if (!filled) {
            #pragma unroll
            for (int kk = 2; kk <= 32; kk <<= 1) {
                #pragma unroll
                for (int j = kk >> 1; j > 0; j >>= 1) {
                    const float ov = __shfl_xor_sync(FULLM, sqv, j);
                    const int   oi = __shfl_xor_sync(FULLM, jj,  j);
                    const bool dirAsc = ((lane & kk) == 0);
                    const bool otherLess = (ov < sqv) || (ov == sqv && oi < jj);
                    const bool lower = (lane & j) == 0;
                    const bool keepOther = lower ? (dirAsc ? otherLess : !otherLess)
                                                 : (dirAsc ? !otherLess : otherLess);
                    if (keepOther) { sqv = ov; jj = oi; }
                }
            }
            lv = sqv; li = jj;
            thr_v = __shfl_sync(FULLM, lv, 31);
            thr_i = __shfl_sync(FULLM, li, 31);
            filled = true;
        } else {
            const bool acc = (sqv < thr_v) || (sqv == thr_v && jj < thr_i);
            unsigned ball = __ballot_sync(FULLM, acc);
            if (ball) {
                do {
                    const int   sl = __ffs(ball) - 1;
                    ball &= ball - 1;
                    const float nv = __shfl_sync(FULLM, sqv, sl);
                    const int   nj = __shfl_sync(FULLM, jj,  sl);
                    const unsigned le =
                        __ballot_sync(FULLM, (lv < nv) || (lv == nv && li < nj));
                    const int ppos = __popc(le);
                    if (ppos < 32) {
                        const float pv = __shfl_up_sync(FULLM, lv, 1);
                        const int   pj = __shfl_up_sync(FULLM, li, 1);
                        if (lane > ppos)       { lv = pv; li = pj; }
                        else if (lane == ppos) { lv = nv; li = nj; }
                    }
                } while (ball);
                thr_v = __shfl_sync(FULLM, lv, 31);
                thr_i = __shfl_sync(FULLM, li, 31);
            }
        }
    };

    // warp-exclusive-scan of per-lane segment lengths into s_p0/s_pre
    auto scan_store = [&](int p0, int len) -> int {
        int pre = len;
        #pragma unroll
        for (int off = 1; off < 32; off <<= 1) {
            int n = __shfl_up_sync(FULLM, pre, off);
            if (lane >= off) pre += n;
        }
        const int total = __shfl_sync(FULLM, pre, 31);
        pre -= len;
        s_p0 [w][lane] = p0;
        s_pre[w][lane] = pre;
        __syncwarp(FULLM);
        return total;
    };

    // stream-position -> pts row (binary search over 32 smem prefix entries)
    auto locate = [&](int pos) -> int {
        int lo = 0;
        #pragma unroll
        for (int step = 16; step; step >>= 1) {
            const int cand = lo + step;
            if (cand < 32 && s_pre[w][cand] <= pos) lo = cand;
        }
        return s_p0[w][lo] + (pos - s_pre[w][lo]);
    };

    // ---- phase 1: d<=1 box as 9 x-merged rows, center row FIRST ----
    {
        int p0 = 0, len = 0;
        if (lane < 9) {
            // proximity order: center row first, then |dy|+|dz| ascending
            const int dy[9] = {0, -1, 1,  0, 0, -1, -1,  1, 1};
            const int dz[9] = {0,  0, 0, -1, 1, -1,  1, -1, 1};
            const int yc = cy + dy[lane];
            const int zc = cz + dz[lane];
            if (yc >= 0 && yc < G && zc >= 0 && zc < G) {
                const int x0 = max(cx - 1, 0), x1 = min(cx + 1, G - 1);
                const int cb = (zc * G + yc) * G;
                p0  = cstart[cb + x0];
                len = cstart[cb + x1 + 1] - p0;
            }
        }
        const int T = scan_store(p0, len);
        const int S = min(T, CAPW);

        // Phase A: independent copy iterations (pipelined search+LDG+STS)
        for (int i = lane; i < S; i += 32) {
            const int ii = locate(i);
            float4 P = pts[ii];
            P.w = __int_as_float(pidx[ii]);   // pack idx for the buffer
            s_buf[w][i] = P;
        }
        __syncwarp(FULLM);

        // Phase B: LDS-linear compute (no search, no LDG)
        for (int base = 0; base < S; base += 32) {
            const int pos = base + lane;
            float sqv = INF; int jj = IMAX;
            if (pos < S) {
                const float4 Sc = s_buf[w][pos];
                jj = __float_as_int(Sc.w);
                const float ss = __fadd_rn(__fadd_rn(__fmul_rn(Sc.x, Sc.x),
                                                     __fmul_rn(Sc.y, Sc.y)),
                                           __fmul_rn(Sc.z, Sc.z));
                const float dot = __fmaf_rn(pz, Sc.z,
                                   __fmaf_rn(py, Sc.y, __fmul_rn(px, Sc.x)));
                sqv = __fadd_rn(__fsub_rn(tt, __fmul_rn(2.0f, dot)), ss);
            }
            consume(sqv, jj);
        }

        // Overflow: continue the same stream via the R5 path (no duplicates)
        for (int base = S; base < T; base += 32) {
            const int pos = base + lane;
            float sqv = INF; int jj = IMAX;
            if (pos < T) {
                const int ii = locate(pos);
                const float4 S4 = pts[ii];
                jj = pidx[ii];
                const float dot = __fmaf_rn(pz, S4.z,
                                   __fmaf_rn(py, S4.y, __fmul_rn(px, S4.x)));
                sqv = __fadd_rn(__fsub_rn(tt, __fmul_rn(2.0f, dot)), S4.w);
            }
            consume(sqv, jj);
        }
    }

    // ---- phase 2: shells d >= 2 (rare; R5 enumeration verbatim) ----
    for (int d = 1;;) {
        const float dm = __fmaf_rn((float)d, GH, -e);
        if (dm > 0.0f && thr_v < dm * dm) break;   // strict: protects index ties
        if (d >= dmax) break;
        ++d;
        const int nseg = 8 * d + 2 * (2 * d - 1) * (2 * d - 1);
        for (int bk = 0; bk < nseg; bk += 32) {
            const int k = bk + lane;
            bool valid = (k < nseg);
            int zc = cz, yc = cy, x0 = cx, x1 = cx;
            if (valid) {
                if (k < 8 * d) {                  // perimeter rows (full span)
                    const int side = k / (2 * d), off = k % (2 * d);
                    int zo, yo;
                    if      (side == 0) { zo = -d; yo = -d + off; }
                    else if (side == 1) { yo =  d; zo = -d + off; }
                    else if (side == 2) { zo =  d; yo =  d - off; }
                    else                { yo = -d; zo =  d - off; }
                    zc = cz + zo; yc = cy + yo;
                    x0 = max(cx - d, 0); x1 = min(cx + d, G - 1);
                } else {                           // inner rows: 2 single cells
                    const int k2 = k - 8 * d;
                    const int w2 = 2 * d - 1;
                    const int r = k2 >> 1, side2 = k2 & 1;
                    zc = cz + (-d + 1 + r / w2);
                    yc = cy + (-d + 1 + r % w2);
                    const int x = side2 ? (cx + d) : (cx - d);
                    x0 = x1 = x;
                    if (x < 0 || x >= G) valid = false;
                }
                if (zc < 0 || zc >= G || yc < 0 || yc >= G) valid = false;
            }
            int p0 = 0, len = 0;
            if (valid) {
                const int cb = (zc * G + yc) * G;
                p0  = cstart[cb + x0];
                len = cstart[cb + x1 + 1] - p0;
            }
            const int total = scan_store(p0, len);
            if (total == 0) continue;

            for (int base = 0; base < total; base += 32) {
                const int pos = base + lane;
                float sqv = INF; int jj = IMAX;
                if (pos < total) {
                    const int ii = locate(pos);
                    const float4 S4 = pts[ii];
                    jj = pidx[ii];
                    const float dot = __fmaf_rn(pz, S4.z,
                                       __fmaf_rn(py, S4.y, __fmul_rn(px, S4.x)));
                    sqv = __fadd_rn(__fsub_rn(tt, __fmul_rn(2.0f, dot)), S4.w);
                }
                consume(sqv, jj);
            }
        }
    }

    // ---- outputs ----
    const float rad  = 0.2f;
    const float rad2 = __fmul_rn(rad, rad);
    const bool  mask = (rad2 >= lv);

    float gx = 0.0f, gy = 0.0f, gz = 0.0f;
    if (mask) {
        const float* sp = src + (size_t)(b * NSRC + li) * 3;
        gx = __fdiv_rn(sp[0], rad);
        gy = __fdiv_rn(sp[1], rad);
        gz = __fdiv_rn(sp[2], rad);
    }
    const float tdx = __fdiv_rn(px, rad);
    const float tdy = __fdiv_rn(py, rad);
    const float tdz = __fdiv_rn(pz, rad);

    const size_t ee = (size_t)tg * KNN + lane;

    float* patches = out + OFF_PATCH;
    patches[3 * ee + 0] = __fsub_rn(gx, tdx);
    patches[3 * ee + 1] = __fsub_rn(gy, tdy);
    patches[3 * ee + 2] = __fsub_rn(gz, tdz);

    float* idxf = out + OFF_IDX;
    idxf[2 * ee + 0] = (float)b;
    idxf[2 * ee + 1] = (float)(mask ? li : -1);

    float* pdist = out + OFF_DIST;
    pdist[ee] = __fdiv_rn(__fsqrt_rn(fmaxf(lv, 1e-9f)), rad);

    const unsigned mball = __ballot_sync(FULLM, mask);
    if (lane == 0) {
        float* psize = out + OFF_SIZE;
        psize[tg] = (float)__popc(mball);
    }

    if (blockIdx.x == 0 && threadIdx.x < NB) {
        float* prad = out + OFF_RAD;
        prad[threadIdx.x] = rad;
    }
}

extern "C" void kernel_launch(void* const* d_in, const int* in_sizes, int n_in,
                              void* d_out, int out_size) {
    const float* src = (const float*)d_in[0];
    const float* tgt = (const float*)d_in[1];
    if (n_in >= 2 && in_sizes[0] == NB * NTGT * 3 && in_sizes[1] == NB * NSRC * 3) {
        src = (const float*)d_in[1];
        tgt = (const float*)d_in[0];
    }
    float* out = (float*)d_out;

    k_zero   <<<(NB * NCELL + 255) / 256, 256>>>();
    k_count  <<<(NB * NSRC + 255) / 256, 256>>>(src);
    k_scan   <<<NB, 1024>>>();
    k_scatter<<<(NB * NSRC + 255) / 256, 256>>>(src);
    k_query  <<<(NB * NTGT) / WPB, 128>>>(src, tgt, out);
}

// round 11
// speedup vs baseline: 1.4211x; 1.2010x over previous
#include <cuda_runtime.h>
#include <cstdint>
#include <cstddef>

#define NB    4
#define NSRC  16384
#define NTGT  4096
#define KNN   32
#define FULLM 0xffffffffu

// spatial grid
#define G     32
#define NCELL (G*G*G)
#define LB    6.0f
#define GH    0.375f
#define INVH  (1.0f/GH)

// Output layout (flattened concat, all float32):
#define OFF_PATCH 0
#define OFF_IDX   1572864
#define OFF_SIZE  2621440
#define OFF_RAD   2637824
#define OFF_DIST  2637828

// __device__ scratch (no allocations allowed)
__device__ int    g_cnt[NB * NCELL];
__device__ int    g_cur[NB * NCELL];
__device__ int    g_start[NB * (NCELL + 1)];
__device__ float4 g_pts[NB * NSRC];   // (x, y, z, sumsq), cell-sorted
__device__ int    g_pidx[NB * NSRC];  // original within-batch index

__device__ __forceinline__ int cellcoord(float v) {
    int c = (int)floorf((v + LB) * INVH);
    return min(G - 1, max(0, c));
}

__global__ void k_zero() {
    int i = blockIdx.x * blockDim.x + threadIdx.x;
    if (i < NB * NCELL) g_cnt[i] = 0;
}

__global__ void k_count(const float* __restrict__ src) {
    int i = blockIdx.x * blockDim.x + threadIdx.x;
    if (i >= NB * NSRC) return;
    int b = i / NSRC;
    float x = src[3 * i], y = src[3 * i + 1], z = src[3 * i + 2];
    int cell = (cellcoord(z) * G + cellcoord(y)) * G + cellcoord(x);
    atomicAdd(&g_cnt[b * NCELL + cell], 1);
}

#define CPT (NCELL / 1024)
__global__ void k_scan() {
    __shared__ int sm[1024];
    int b = blockIdx.x, t = threadIdx.x;
    const int* cnt = g_cnt + b * NCELL;
    int* start = g_start + b * (NCELL + 1);
    int* cur   = g_cur + b * NCELL;
    int s = 0;
    #pragma unroll
    for (int c = 0; c < CPT; c++) s += cnt[t * CPT + c];
    sm[t] = s; __syncthreads();
    for (int off = 1; off < 1024; off <<= 1) {
        int v = (t >= off) ? sm[t - off] : 0;
        __syncthreads();
        sm[t] += v;
        __syncthreads();
    }
    int run = sm[t] - s;
    #pragma unroll
    for (int c = 0; c < CPT; c++) {
        int id = t * CPT + c;
        start[id] = run; cur[id] = run;
        run += cnt[id];
    }
    if (t == 1023) start[NCELL] = NSRC;
}

__global__ void k_scatter(const float* __restrict__ src) {
    int i = blockIdx.x * blockDim.x + threadIdx.x;
    if (i >= NB * NSRC) return;
    int b = i / NSRC;
    float x = src[3 * i], y = src[3 * i + 1], z = src[3 * i + 2];
    int cell = (cellcoord(z) * G + cellcoord(y)) * G + cellcoord(x);
    int pos = atomicAdd(&g_cur[b * NCELL + cell], 1);
    float ss = __fadd_rn(__fadd_rn(__fmul_rn(x, x), __fmul_rn(y, y)), __fmul_rn(z, z));
    g_pts[b * NSRC + pos]  = make_float4(x, y, z, ss);
    g_pidx[b * NSRC + pos] = i - b * NSRC;
}

// One warp per target. Exact KNN via expanding Chebyshev shells (R5 control
// flow). Top-K warp-sorted ascending under lexicographic (value, index) order
// == jax top_k tie-break; min-32-of-union is scan-order invariant, so the
// batch-merge fast path below selects the identical set.
__global__ __launch_bounds__(256) void k_query(const float* __restrict__ src,
                                               const float* __restrict__ tgt,
                                               float* __restrict__ out) {
    __shared__ int s_p0 [8][32];
    __shared__ int s_pre[8][32];

    const int w    = threadIdx.x >> 5;
    const int lane = threadIdx.x & 31;
    const int tg   = blockIdx.x * 8 + w;
    const int b    = tg / NTGT;

    const float px = tgt[3 * tg], py = tgt[3 * tg + 1], pz = tgt[3 * tg + 2];
    const float tt = __fadd_rn(__fadd_rn(__fmul_rn(px, px), __fmul_rn(py, py)),
                               __fmul_rn(pz, pz));

    const int cx = cellcoord(px), cy = cellcoord(py), cz = cellcoord(pz);
    float ex = fmaxf(fmaxf(-LB - px, px - LB), 0.0f);
    float ey = fmaxf(fmaxf(-LB - py, py - LB), 0.0f);
    float ez = fmaxf(fmaxf(-LB - pz, pz - LB), 0.0f);
    const float e = sqrtf(ex * ex + ey * ey + ez * ez);

    const float INF  = __int_as_float(0x7f800000);
    const int   IMAX = 0x7fffffff;
    float lv = INF; int li = IMAX;
    float thr_v = INF; int thr_i = IMAX;
    bool filled = false;

    const int*    cstart = g_start + b * (NCELL + 1);
    const float4* pts    = g_pts + b * NSRC;
    const int*    pidx   = g_pidx + b * NSRC;

    const int dmax = max(max(max(cx, G - 1 - cx), max(cy, G - 1 - cy)),
                         max(cz, G - 1 - cz));

    // ascending-lex bitonic sort of one (value,index) per lane
    auto sort32 = [&](float& v, int& ix) {
        #pragma unroll
        for (int kk = 2; kk <= 32; kk <<= 1) {
            #pragma unroll
            for (int j = kk >> 1; j > 0; j >>= 1) {
                const float ov = __shfl_xor_sync(FULLM, v, j);
                const int   oi = __shfl_xor_sync(FULLM, ix, j);
                const bool dirAsc = ((lane & kk) == 0);
                const bool otherLess = (ov < v) || (ov == v && oi < ix);
                const bool lower = (lane & j) == 0;
                const bool keepOther = lower ? (dirAsc ? otherLess : !otherLess)
                                             : (dirAsc ? !otherLess : otherLess);
                if (keepOther) { v = ov; ix = oi; }
            }
        }
    };

    for (int d = 0;; ++d) {
        const int nseg = (d == 0) ? 1 : (8 * d + 2 * (2 * d - 1) * (2 * d - 1));
        for (int bk = 0; bk < nseg; bk += 32) {
            // ---- lane-parallel segment ranges ----
            const int k = bk + lane;
            bool valid = (k < nseg);
            int zc = cz, yc = cy, x0 = cx, x1 = cx;
            if (valid && d > 0) {
                if (k < 8 * d) {                 // perimeter rows (full x span)
                    const int side = k / (2 * d), off = k % (2 * d);
                    int zo, yo;
                    if      (side == 0) { zo = -d;       yo = -d + off; }
                    else if (side == 1) { yo =  d;       zo = -d + off; }
                    else if (side == 2) { zo =  d;       yo =  d - off; }
                    else                { yo = -d;       zo =  d - off; }
                    zc = cz + zo; yc = cy + yo;
                    x0 = max(cx - d, 0); x1 = min(cx + d, G - 1);
                } else {                          // inner rows: 2 single cells
                    const int k2 = k - 8 * d;
                    const int w2 = 2 * d - 1;
                    const int r = k2 >> 1, side = k2 & 1;
                    zc = cz + (-d + 1 + r / w2);
                    yc = cy + (-d + 1 + r % w2);
                    const int x = side ? (cx + d) : (cx - d);
                    x0 = x1 = x;
                    if (x < 0 || x >= G) valid = false;
                }
                if (zc < 0 || zc >= G || yc < 0 || yc >= G) valid = false;
            }
            int p0 = 0, len = 0;
            if (valid) {
                const int cb = (zc * G + yc) * G;
                p0  = cstart[cb + x0];
                len = cstart[cb + x1 + 1] - p0;
            }
            // exclusive warp scan of len
            int pre = len;
            #pragma unroll
            for (int off = 1; off < 32; off <<= 1) {
                int n = __shfl_up_sync(FULLM, pre, off);
                if (lane >= off) pre += n;
            }
            const int total = __shfl_sync(FULLM, pre, 31);
            pre -= len;
            s_p0 [w][lane] = p0;
            s_pre[w][lane] = pre;
            __syncwarp(FULLM);
            if (total == 0) continue;

            // ---- flat candidate stream ----
            for (int base = 0; base < total; base += 32) {
                const int pos = base + lane;
                float sqv = INF; int jj = IMAX;
                if (pos < total) {
                    int lo = 0;              // max s with pre[s] <= pos
                    #pragma unroll
                    for (int step = 16; step; step >>= 1) {
                        const int cand = lo + step;
                        if (cand < 32 && s_pre[w][cand] <= pos) lo = cand;
                    }
                    const int ii = s_p0[w][lo] + (pos - s_pre[w][lo]);
                    const float4 S = pts[ii];
                    jj = pidx[ii];
                    float dot = __fmaf_rn(pz, S.z,
                                 __fmaf_rn(py, S.y, __fmul_rn(px, S.x)));
                    sqv = __fadd_rn(__fsub_rn(tt, __fmul_rn(2.0f, dot)), S.w);
                }

                if (filled) {
                    const bool acc = (sqv < thr_v) || (sqv == thr_v && jj < thr_i);
                    unsigned ball = __ballot_sync(FULLM, acc);
                    const int nacc = __popc(ball);
                    if (nacc == 0) continue;
                    if (nacc < 8) {
                        // serial insertion (cheap for sparse accepts)
                        do {
                            const int   sl = __ffs(ball) - 1;
                            ball &= ball - 1;
                            const float nv = __shfl_sync(FULLM, sqv, sl);
                            const int   nj = __shfl_sync(FULLM, jj,  sl);
                            const unsigned le =
                                __ballot_sync(FULLM, (lv < nv) || (lv == nv && li < nj));
                            const int ppos = __popc(le);
                            if (ppos < 32) {
                                const float pv = __shfl_up_sync(FULLM, lv, 1);
                                const int   pj = __shfl_up_sync(FULLM, li, 1);
                                if (lane > ppos)       { lv = pv; li = pj; }
                                else if (lane == ppos) { lv = nv; li = nj; }
                            }
                        } while (ball);
                        thr_v = __shfl_sync(FULLM, lv, 31);
                        thr_i = __shfl_sync(FULLM, li, 31);
                        continue;
                    }
                    // dense accepts: batch sort + bitonic merge (constant depth)
                    if (!acc) { sqv = INF; jj = IMAX; }
                    sort32(sqv, jj);
                    // concat(lv asc, batch desc) is bitonic; halver keeps 32 mins
                    const float bv = __shfl_sync(FULLM, sqv, 31 - lane);
                    const int   bi = __shfl_sync(FULLM, jj,  31 - lane);
                    const bool keepB = (bv < lv) || (bv == lv && bi < li);
                    float cv = keepB ? bv : lv;
                    int   ci = keepB ? bi : li;
                    // 5-stage bitonic merge, ascending lex
                    #pragma unroll
                    for (int j = 16; j; j >>= 1) {
                        const float ov = __shfl_xor_sync(FULLM, cv, j);
                        const int   oi = __shfl_xor_sync(FULLM, ci, j);
                        const bool otherLess = (ov < cv) || (ov == cv && oi < ci);
                        const bool lower = (lane & j) == 0;
                        if (lower ? otherLess : !otherLess) { cv = ov; ci = oi; }
                    }
                    lv = cv; li = ci;
                    thr_v = __shfl_sync(FULLM, lv, 31);
                    thr_i = __shfl_sync(FULLM, li, 31);
                } else {
                    // initial fill: sort the first batch, take as list
                    sort32(sqv, jj);
                    lv = sqv; li = jj;
                    thr_v = __shfl_sync(FULLM, lv, 31);
                    thr_i = __shfl_sync(FULLM, li, 31);
                    filled = true;
                }
            }
        }
        const float dm = __fmaf_rn((float)d, GH, -e);
        if (dm > 0.0f && thr_v < dm * dm) break;   // strict: protects index ties
        if (d >= dmax) break;
    }

    // ---- outputs ----
    const float rad  = 0.2f;
    const float rad2 = __fmul_rn(rad, rad);
    const bool  mask = (rad2 >= lv);

    float gx = 0.0f, gy = 0.0f, gz = 0.0f;
    if (mask) {
        const float* sp = src + (size_t)(b * NSRC + li) * 3;
        gx = __fdiv_rn(sp[0], rad);
        gy = __fdiv_rn(sp[1], rad);
        gz = __fdiv_rn(sp[2], rad);
    }
    const float tdx = __fdiv_rn(px, rad);
    const float tdy = __fdiv_rn(py, rad);
    const float tdz = __fdiv_rn(pz, rad);

    const size_t ee = (size_t)tg * KNN + lane;

    float* patches = out + OFF_PATCH;
    patches[3 * ee + 0] = __fsub_rn(gx, tdx);
    patches[3 * ee + 1] = __fsub_rn(gy, tdy);
    patches[3 * ee + 2] = __fsub_rn(gz, tdz);

    float* idxf = out + OFF_IDX;
    idxf[2 * ee + 0] = (float)b;
    idxf[2 * ee + 1] = (float)(mask ? li : -1);

    float* pdist = out + OFF_DIST;
    pdist[ee] = __fdiv_rn(__fsqrt_rn(fmaxf(lv, 1e-9f)), rad);

    const unsigned mball = __ballot_sync(FULLM, mask);
    if (lane == 0) {
        float* psize = out + OFF_SIZE;
        psize[tg] = (float)__popc(mball);
    }

    if (blockIdx.x == 0 && threadIdx.x < NB) {
        float* prad = out + OFF_RAD;
        prad[threadIdx.x] = rad;
    }
}

extern "C" void kernel_launch(void* const* d_in, const int* in_sizes, int n_in,
                              void* d_out, int out_size) {
    const float* src = (const float*)d_in[0];
    const float* tgt = (const float*)d_in[1];
    if (n_in >= 2 && in_sizes[0] == NB * NTGT * 3 && in_sizes[1] == NB * NSRC * 3) {
        src = (const float*)d_in[1];
        tgt = (const float*)d_in[0];
    }
    float* out = (float*)d_out;

    k_zero   <<<(NB * NCELL + 255) / 256, 256>>>();
    k_count  <<<(NB * NSRC + 255) / 256, 256>>>(src);
    k_scan   <<<NB, 1024>>>();
    k_scatter<<<(NB * NSRC + 255) / 256, 256>>>(src);
    k_query  <<<(NB * NTGT) / 8, 256>>>(src, tgt, out);
}